// round 15
// baseline (speedup 1.0000x reference)
#include <cuda_runtime.h>
#include <cuda_bf16.h>

#define T_IN   4096
#define T2     8192
#define C_CH   512
#define B_N    16
#define THREADS 128
#define TOUT    8
#define SEGS   4
#define SXN    1048    // staged x: raw [start-12, start+1035], edge-clamped
#define SYN    2064    // staged y: logical j = u - (2*start - 8), j in [0,2064)

// kaiser_sinc_filter1d(0.25, 0.3, 12) — precomputed, symmetric (h[k]==h[11-k]).
#define H0 0.00202897f
#define H1 0.00938893f
#define H2 (-0.02554347f)
#define H3 (-0.05765742f)
#define H4 0.12857272f
#define H5 0.44321013f

// even u=2s:   y = sum_m UE[m]*x[s+m-3],  UE[m] = 2*h[11-2m]
// odd  u=2s+1: y = sum_m UO[m]*x[s+m-2],  UO[m] = 2*h[10-2m]
__device__ constexpr float UE[6] = { 2.0f*H0, 2.0f*H2, 2.0f*H4, 2.0f*H5, 2.0f*H3, 2.0f*H1 };
__device__ constexpr float UO[6] = { 2.0f*H1, 2.0f*H3, 2.0f*H5, 2.0f*H4, 2.0f*H2, 2.0f*H0 };
__device__ constexpr float DD[12] = { H0, H1, H2, H3, H4, H5, H5, H4, H3, H2, H1, H0 };

__global__ __launch_bounds__(THREADS, 12)   // ~42-reg budget; smem caps ~12 blocks anyway
void aa_act_kernel(const float* __restrict__ x,
                   const float* __restrict__ alpha,
                   const float* __restrict__ beta,
                   const float* __restrict__ uf,   // unused: taps are immediates
                   const float* __restrict__ df,   // unused
                   float* __restrict__ out)
{
    __shared__ __align__(16) float sx[SXN];
    __shared__ __align__(16) float sy[SYN];

    const int bx    = blockIdx.x;
    const int r     = bx >> 2;        // row = b*C + c
    const int seg   = bx & 3;
    const int start = seg << 10;
    const int c     = r & (C_CH - 1);
    const int tid   = threadIdx.x;
    const int base  = start - 12;     // raw x index of sx[0]

    const float* xrow = x + (size_t)r * T_IN;
    float* orow       = out + (size_t)r * T_IN;

    // ---- Stage x segment (+halo 12), edge-clamped. (champion's staging, unchanged)
#pragma unroll
    for (int it = 0; it < 9; ++it) {
        int i = tid + it * THREADS;
        if (i < SXN) {
            int gi = base + i;
            gi = gi < 0 ? 0 : (gi > T_IN - 1 ? T_IN - 1 : gi);
            sx[i] = __ldg(xrow + gi);
        }
    }

    const float ea    = __expf(__ldg(alpha + c));
    const float ieb   = 1.0f / (__expf(__ldg(beta + c)) + 1e-9f);
    const float ea2   = 2.0f * ea;     // snake uses cos(2*ea*y)
    const float ieb2  = 0.5f * ieb;    // snake: y + ieb2 - ieb2*cos(2*ea*y)
    const float nieb2 = -ieb2;

    __syncthreads();

    // ================= PASS 1: each y computed once =================
    // sy[j] = partial-snaked y[u], u = 2*start - 8 + j  (constant +ieb2 folded into
    // pass-2 accumulator init, since down-filter taps sum to exactly 1).
    // Thread t computes j = 16t .. 16t+15:
    //   j = 2i   (even u): s = start-4+8t+i, y = sum_m UE[m] x[s+m-3] = sum UE[m] rx[i+1+m]
    //   j = 2i+1 (odd  u): same s,          y = sum_m UO[m] x[s+m-2] = sum UO[m] rx[i+2+m]
    // with rx[k] = x[s0-4+k], s0 = start-4+8t  ->  rx = sx[8t+4 .. 8t+19] (float4 idx 2t+1).
    {
        float rx[16];
        const float4* s4 = reinterpret_cast<const float4*>(sx);
#pragma unroll
        for (int i = 0; i < 4; i++) {
            float4 v = s4[2 * tid + 1 + i];
            rx[4 * i + 0] = v.x; rx[4 * i + 1] = v.y;
            rx[4 * i + 2] = v.z; rx[4 * i + 3] = v.w;
        }

        float4* sy4 = reinterpret_cast<float4*>(sy);
#pragma unroll
        for (int cc = 0; cc < 4; ++cc) {
            float4 w;
#pragma unroll
            for (int h = 0; h < 2; ++h) {
                const int i = 2 * cc + h;
                float ye = UE[0] * rx[i + 1];
                float yo = UO[0] * rx[i + 2];
#pragma unroll
                for (int m = 1; m < 6; ++m) {
                    ye = fmaf(UE[m], rx[i + 1 + m], ye);
                    yo = fmaf(UO[m], rx[i + 2 + m], yo);
                }
                float ce = __cosf(ye * ea2);
                float co = __cosf(yo * ea2);
                ye = fmaf(nieb2, ce, ye);
                yo = fmaf(nieb2, co, yo);
                if (h == 0) { w.x = ye; w.y = yo; }
                else        { w.z = ye; w.w = yo; }
            }
            sy4[4 * tid + cc] = w;
        }
    }

    // Tail: j = 2048..2063 (16 extra y), threads 0..3, 4 each (scalar sx reads).
    if (tid < 4) {
#pragma unroll
        for (int e = 0; e < 4; ++e) {
            const int j = 2048 + 4 * tid + e;
            const int u = 2 * start - 8 + j;
            const int s = u >> 1;
            const int idx = s - base;
            float yv;
            if (u & 1) {
                yv = UO[0] * sx[idx - 2];
#pragma unroll
                for (int m = 1; m < 6; ++m) yv = fmaf(UO[m], sx[idx + m - 2], yv);
            } else {
                yv = UE[0] * sx[idx - 3];
#pragma unroll
                for (int m = 1; m < 6; ++m) yv = fmaf(UE[m], sx[idx + m - 3], yv);
            }
            float cc2 = __cosf(yv * ea2);
            sy[j] = fmaf(nieb2, cc2, yv);
        }
    }

    __syncthreads();

    // ================= PASS 2: downsample scatter =================
    const int t0 = start + tid * TOUT;
    const bool fast_ok = (t0 >= 3) && (t0 <= 4085);

    if (fast_ok) {
        // out[t0+q] needs sy[16*tid + 2q+3 + k], k=0..11  (j_off = 2q+3+k in [3,28])
        float acc[TOUT];
#pragma unroll
        for (int q = 0; q < TOUT; q++) acc[q] = ieb2;   // folded snake constant

        const float4* sy4 = reinterpret_cast<const float4*>(sy);
#pragma unroll
        for (int cc = 0; cc < 8; ++cc) {
            float4 v = sy4[4 * tid + cc];
            float ve[4] = { v.x, v.y, v.z, v.w };
#pragma unroll
            for (int e = 0; e < 4; ++e) {
                const int joff = 4 * cc + e;
#pragma unroll
                for (int q = 0; q < TOUT; ++q) {
                    const int k = joff - 2 * q - 3;
                    if (k >= 0 && k < 12) acc[q] = fmaf(DD[k], ve[e], acc[q]);
                }
            }
        }

        *reinterpret_cast<float4*>(orow + t0)     = make_float4(acc[0], acc[1], acc[2], acc[3]);
        *reinterpret_cast<float4*>(orow + t0 + 4) = make_float4(acc[4], acc[5], acc[6], acc[7]);
    } else {
        // Edge path (t0==0 or t0==4088): clamp global y index, read sy scalar.
        float acc[TOUT];
#pragma unroll
        for (int q = 0; q < TOUT; q++) acc[q] = ieb2;

#pragma unroll 1
        for (int jj = 0; jj < 26; ++jj) {
            int u = 2 * t0 - 5 + jj;
            u = u < 0 ? 0 : (u > T2 - 1 ? T2 - 1 : u);
            const float yv = sy[u - (2 * start - 8)];
#pragma unroll
            for (int q = 0; q < TOUT; ++q) {
                const int k = jj - 2 * q;
                if (k >= 0 && k < 12) acc[q] = fmaf(DD[k], yv, acc[q]);
            }
        }
#pragma unroll
        for (int q = 0; q < TOUT; q++) orow[t0 + q] = acc[q];
    }
}

extern "C" void kernel_launch(void* const* d_in, const int* in_sizes, int n_in,
                              void* d_out, int out_size) {
    const float* x     = (const float*)d_in[0];
    const float* alpha = (const float*)d_in[1];
    const float* beta  = (const float*)d_in[2];
    const float* uf    = (const float*)d_in[3];
    const float* df    = (const float*)d_in[4];
    float* out = (float*)d_out;

    dim3 grid(B_N * C_CH * SEGS);   // 32768 blocks
    aa_act_kernel<<<grid, THREADS>>>(x, alpha, beta, uf, df, out);
}

// round 16
// speedup vs baseline: 2.0776x; 2.0776x over previous
#include <cuda_runtime.h>
#include <cuda_bf16.h>

#define T_IN   4096
#define T2     8192
#define C_CH   512
#define B_N    16
#define THREADS 128
#define TOUT    8
#define NOUT_BLK 1024
#define SEGS   4
#define SXN    1048    // staged x: raw [start-12, start+1035], edge-clamped (262 float4)

// kaiser_sinc_filter1d(0.25, 0.3, 12) — precomputed, symmetric (h[k]==h[11-k]).
#define H0 0.00202897f
#define H1 0.00938893f
#define H2 (-0.02554347f)
#define H3 (-0.05765742f)
#define H4 0.12857272f
#define H5 0.44321013f

// Up-sampling polyphase taps (2x gain folded in):
// even u=2s:   y = sum_m UE[m]*x[s+m-3],  UE[m] = 2*h[11-2m]
// odd  u=2s+1: y = sum_m UO[m]*x[s+m-2],  UO[m] = 2*h[10-2m]
__device__ constexpr float UE[6] = { 2.0f*H0, 2.0f*H2, 2.0f*H4, 2.0f*H5, 2.0f*H3, 2.0f*H1 };
__device__ constexpr float UO[6] = { 2.0f*H1, 2.0f*H3, 2.0f*H5, 2.0f*H4, 2.0f*H2, 2.0f*H0 };
// Down-sampling taps
__device__ constexpr float DD[12] = { H0, H1, H2, H3, H4, H5, H5, H4, H3, H2, H1, H0 };

__global__ __launch_bounds__(THREADS)
void aa_act_kernel(const float* __restrict__ x,
                   const float* __restrict__ alpha,
                   const float* __restrict__ beta,
                   const float* __restrict__ uf,   // unused: taps are immediates
                   const float* __restrict__ df,   // unused
                   float* __restrict__ out)
{
    __shared__ __align__(16) float sx[SXN];

    const int bx    = blockIdx.x;
    const int r     = bx >> 2;        // row = b*C + c
    const int seg   = bx & 3;
    const int start = seg << 10;
    const int c     = r & (C_CH - 1);
    const int tid   = threadIdx.x;
    const int base  = start - 12;     // raw x index of sx[0]

    const float* xrow = x + (size_t)r * T_IN;
    float* orow       = out + (size_t)r * T_IN;

    // ---- Vectorized staging: sx[i] = x[clamp(base+i)]  (base float4-aligned) ----
    {
        float4* dst4 = reinterpret_cast<float4*>(sx);
        if (seg == 0) {
            // sx[0..11] = x[0] (left clamp); sx[12..1047] = x[0..1035] (259 float4)
            const float4* s4p = reinterpret_cast<const float4*>(xrow);
#pragma unroll
            for (int it = 0; it < 3; ++it) {
                int i = tid + it * THREADS;
                if (i < 259) dst4[i + 3] = __ldg(s4p + i);
            }
            if (tid < 12) sx[tid] = __ldg(xrow);
        } else if (seg == 3) {
            // sx[0..1035] = x[3060..4095] (259 float4); sx[1036..1047] = x[4095]
            const float4* s4p = reinterpret_cast<const float4*>(xrow + 3060);
#pragma unroll
            for (int it = 0; it < 3; ++it) {
                int i = tid + it * THREADS;
                if (i < 259) dst4[i] = __ldg(s4p + i);
            }
            if (tid < 12) sx[1036 + tid] = __ldg(xrow + (T_IN - 1));
        } else {
            // interior: sx[0..1047] = x[start-12 .. start+1035] (262 float4)
            const float4* s4p = reinterpret_cast<const float4*>(xrow + (start - 12));
#pragma unroll
            for (int it = 0; it < 3; ++it) {
                int i = tid + it * THREADS;
                if (i < 262) dst4[i] = __ldg(s4p + i);
            }
        }
    }

    const float ea    = __expf(__ldg(alpha + c));
    const float ieb   = 1.0f / (__expf(__ldg(beta + c)) + 1e-9f);
    const float ea2   = 2.0f * ea;     // snake uses cos(2*ea*y)
    const float ieb2  = 0.5f * ieb;    // snake: y + ieb2 - ieb2*cos(2*ea*y)
    const float nieb2 = -ieb2;

    __syncthreads();

    const int t0 = start + tid * TOUT;
    const bool fast_ok = (t0 >= 3) && (t0 <= 4085);

    if (fast_ok) {
        // x window: raw [t0-8, t0+15] -> rx[0..23]; local float4 index 2*tid+1 (16B aligned)
        float rx[24];
        const float4* s4 = reinterpret_cast<const float4*>(sx);
        const int q4 = 2 * tid + 1;
#pragma unroll
        for (int i = 0; i < 6; i++) {
            float4 v = s4[q4 + i];
            rx[4 * i + 0] = v.x; rx[4 * i + 1] = v.y;
            rx[4 * i + 2] = v.z; rx[4 * i + 3] = v.w;
        }

        float acc[8];
#pragma unroll
        for (int q = 0; q < 8; q++) acc[q] = ieb2;   // folded snake constant (taps sum to 1)

        // y index u = 2*t0 - 5 + j, j = 0..25.
        // j = 2i   -> u odd  : yo = sum_m UO[m]*rx[i+3+m]
        // j = 2i+1 -> u even : ye = sum_m UE[m]*rx[i+3+m]
#pragma unroll
        for (int i = 0; i < 13; ++i) {
            float yo = UO[0] * rx[i + 3];
            float ye = UE[0] * rx[i + 3];
#pragma unroll
            for (int m = 1; m < 6; ++m) {
                yo = fmaf(UO[m], rx[i + 3 + m], yo);
                ye = fmaf(UE[m], rx[i + 3 + m], ye);
            }
            // snake (3 ops): w = y - ieb2*cos(2*ea*y)   (+ieb2 folded into acc init)
            float co = __cosf(yo * ea2);
            float ce = __cosf(ye * ea2);
            yo = fmaf(nieb2, co, yo);
            ye = fmaf(nieb2, ce, ye);
            // scatter: y[j] feeds acc[q] with tap k = j - 2q, 0 <= k < 12
#pragma unroll
            for (int q = 0; q < 8; ++q) {
                const int k0 = 2 * i - 2 * q;       // for yo (j = 2i)
                if (k0 >= 0 && k0 < 12) acc[q] = fmaf(DD[k0], yo, acc[q]);
                const int k1 = 2 * i + 1 - 2 * q;   // for ye (j = 2i+1)
                if (k1 >= 0 && k1 < 12) acc[q] = fmaf(DD[k1], ye, acc[q]);
            }
        }

        *reinterpret_cast<float4*>(orow + t0)     = make_float4(acc[0], acc[1], acc[2], acc[3]);
        *reinterpret_cast<float4*>(orow + t0 + 4) = make_float4(acc[4], acc[5], acc[6], acc[7]);
    } else {
        // Edge path (t0==0 or t0==4088): same structure with y-index clamping.
        float acc[8];
#pragma unroll
        for (int q = 0; q < 8; q++) acc[q] = ieb2;

#pragma unroll
        for (int j = 0; j < 26; ++j) {
            int u = 2 * t0 - 5 + j;
            u = u < 0 ? 0 : (u > T2 - 1 ? T2 - 1 : u);
            const int s   = u >> 1;
            const int idx = s - base;          // sx index of x[s]
            float yv;
            if (u & 1) {
                yv = UO[0] * sx[idx - 2];
#pragma unroll
                for (int m = 1; m < 6; ++m) yv = fmaf(UO[m], sx[idx + m - 2], yv);
            } else {
                yv = UE[0] * sx[idx - 3];
#pragma unroll
                for (int m = 1; m < 6; ++m) yv = fmaf(UE[m], sx[idx + m - 3], yv);
            }
            float cc = __cosf(yv * ea2);
            yv = fmaf(nieb2, cc, yv);
#pragma unroll
            for (int q = 0; q < 8; ++q) {
                const int k = j - 2 * q;
                if (k >= 0 && k < 12) acc[q] = fmaf(DD[k], yv, acc[q]);
            }
        }
#pragma unroll
        for (int q = 0; q < 8; q++) orow[t0 + q] = acc[q];
    }
}

extern "C" void kernel_launch(void* const* d_in, const int* in_sizes, int n_in,
                              void* d_out, int out_size) {
    const float* x     = (const float*)d_in[0];
    const float* alpha = (const float*)d_in[1];
    const float* beta  = (const float*)d_in[2];
    const float* uf    = (const float*)d_in[3];
    const float* df    = (const float*)d_in[4];
    float* out = (float*)d_out;

    dim3 grid(B_N * C_CH * SEGS);   // 32768 blocks
    aa_act_kernel<<<grid, THREADS>>>(x, alpha, beta, uf, df, out);
}